// round 12
// baseline (speedup 1.0000x reference)
#include <cuda_runtime.h>
#include <math.h>
#include <stdint.h>

#define Bv 8
#define Tv 2048
#define Hv 1024
#define Mv (Bv*Tv)          // 16384 tokens
#define HOP 12
#define THRESH 0.9f
#define LN_EPS 1e-5f
#define H4 (Hv/4)           // 256

// ---- scratch (static device globals; no allocation) ----
__device__ float g_wtr[Hv*Hv];          // Wt, tf32-rounded, [o][k]
__device__ float g_basep[(size_t)Mv*Hv];// base, tf32-rounded, uint4-interleaved
__device__ float g_c[HOP*Hv];           // c_k[o] = pos_k @ Wt^T + bt  (exact)
__device__ float g_kc[64];              // 0..11 P1, 12..23 P2, 24..35 Pgw, 36 sgw, 37 bw
__device__ float g_alpha[Mv];
__device__ float g_gamma[Mv*HOP];

// ======================= PTX helpers =================================
__device__ __forceinline__ uint32_t f2tf(float f) {
    uint32_t u;
    asm("cvt.rna.tf32.f32 %0, %1;" : "=r"(u) : "f"(f));
    return u;
}
__device__ __forceinline__ uint32_t smem_u32(const void* p) {
    uint32_t a;
    asm("{ .reg .u64 t; cvta.to.shared.u64 t, %1; cvt.u32.u64 %0, t; }"
        : "=r"(a) : "l"(p));
    return a;
}
__device__ __forceinline__ void cpasync16(uint32_t dst, const void* src) {
    asm volatile("cp.async.cg.shared.global [%0], [%1], 16;" :: "r"(dst), "l"(src));
}
#define CP_COMMIT() asm volatile("cp.async.commit_group;" ::: "memory")
#define CP_WAIT(n)  asm volatile("cp.async.wait_group %0;" :: "n"(n) : "memory")

__device__ __forceinline__ void mma_tf32(float c[4], uint32_t a0, uint32_t a1,
                                         uint32_t a2, uint32_t a3,
                                         uint32_t b0, uint32_t b1) {
    asm volatile(
        "mma.sync.aligned.m16n8k8.row.col.f32.tf32.tf32.f32 "
        "{%0,%1,%2,%3}, {%4,%5,%6,%7}, {%8,%9}, {%0,%1,%2,%3};"
        : "+f"(c[0]), "+f"(c[1]), "+f"(c[2]), "+f"(c[3])
        : "r"(a0), "r"(a1), "r"(a2), "r"(a3), "r"(b0), "r"(b1));
}

// =====================================================================
// K1: per-hop scalar constants. 1 block, 256 threads.
// =====================================================================
__global__ void k_scal(const float* __restrict__ pos,
                       const float* __restrict__ gamma,
                       const float* __restrict__ beta,
                       const float* __restrict__ wp) {
    int tid = threadIdx.x;
    float vals[38];
    #pragma unroll
    for (int q = 0; q < 38; q++) vals[q] = 0.0f;
    for (int h = tid; h < Hv; h += 256) {
        float w  = wp[h];
        float gw = gamma[h] * w;
        vals[36] += gw;
        vals[37] += beta[h] * w;
        #pragma unroll
        for (int k = 0; k < HOP; k++) {
            float v = pos[k * Hv + h];
            vals[k]      += v;
            vals[12 + k] += v * v;
            vals[24 + k] += v * gw;
        }
    }
    __shared__ float red[256];
    for (int q = 0; q < 38; q++) {
        red[tid] = vals[q];
        __syncthreads();
        for (int s = 128; s; s >>= 1) {
            if (tid < s) red[tid] += red[tid + s];
            __syncthreads();
        }
        if (tid == 0) g_kc[q] = red[0];
        __syncthreads();
    }
}

// =====================================================================
// K2: per-token stats + scalar ACT loop.  Writes g_basep (tf32-rounded
// base in uint4-fragment interleave):
//   uint4 at (j, kp) = (E[2kp], O[2kp], E[2kp+1], O[2kp+1]),
//   E = token 2j, O = token 2j+1.
// =====================================================================
__global__ __launch_bounds__(256) void k_token(
    const float* __restrict__ inp, const float* __restrict__ tenc,
    const float* __restrict__ pos, const float* __restrict__ gamma,
    const float* __restrict__ wp, const float* __restrict__ bp,
    float* __restrict__ out)
{
    __shared__ float4 s_pos[HOP * H4];   // 48KB
    int tid = threadIdx.x;
    for (int i = tid; i < HOP * H4; i += 256)
        s_pos[i] = ((const float4*)pos)[i];
    __syncthreads();

    int warp = tid >> 5, lane = tid & 31;
    int m = blockIdx.x * 8 + warp;
    int t = m & (Tv - 1);
    int jp = m >> 1, half = m & 1;

    const float4* ip = (const float4*)inp + (size_t)m * H4;
    const float4* tp = (const float4*)tenc + (size_t)t * H4;
    const float4* gp = (const float4*)gamma;
    const float4* wpp = (const float4*)wp;

    float S1 = 0.0f, S2 = 0.0f, A = 0.0f, D[HOP];
    #pragma unroll
    for (int k = 0; k < HOP; k++) D[k] = 0.0f;

    #pragma unroll
    for (int i = 0; i < H4 / 32; i++) {
        int h4 = lane + 32 * i;
        float4 a = ip[h4], b = tp[h4];
        float4 x = make_float4(a.x + b.x, a.y + b.y, a.z + b.z, a.w + b.w);
        {
            size_t wb = ((size_t)jp * 512 + 2 * h4) * 4 + half;
            g_basep[wb]     = __uint_as_float(f2tf(x.x));
            g_basep[wb + 2] = __uint_as_float(f2tf(x.y));
            g_basep[wb + 4] = __uint_as_float(f2tf(x.z));
            g_basep[wb + 6] = __uint_as_float(f2tf(x.w));
        }
        float4 g = gp[h4], w = wpp[h4];
        S1 += x.x + x.y + x.z + x.w;
        S2 += x.x * x.x + x.y * x.y + x.z * x.z + x.w * x.w;
        A  += x.x * (g.x * w.x) + x.y * (g.y * w.y)
            + x.z * (g.z * w.z) + x.w * (g.w * w.w);
        #pragma unroll
        for (int k = 0; k < HOP; k++) {
            float4 pv = s_pos[k * H4 + h4];
            D[k] += x.x * pv.x + x.y * pv.y + x.z * pv.z + x.w * pv.w;
        }
    }
    #pragma unroll
    for (int s = 16; s; s >>= 1) {
        S1 += __shfl_xor_sync(0xffffffffu, S1, s);
        S2 += __shfl_xor_sync(0xffffffffu, S2, s);
        A  += __shfl_xor_sync(0xffffffffu, A,  s);
        #pragma unroll
        for (int k = 0; k < HOP; k++)
            D[k] += __shfl_xor_sync(0xffffffffu, D[k], s);
    }

    if (lane == 0) {
        float sgw = g_kc[36], bw = g_kc[37], bpv = bp[0];
        float hp = 0.0f, rem = 0.0f, nup = 0.0f;
        float uw[HOP];
        #pragma unroll
        for (int k = 0; k < HOP; k++) {
            float mu  = (S1 + g_kc[k]) * (1.0f / Hv);
            float e2  = (S2 + 2.0f * D[k] + g_kc[12 + k]) * (1.0f / Hv);
            float var = e2 - mu * mu;
            float inv = 1.0f / sqrtf(var + LN_EPS);
            float logit = inv * (A + g_kc[24 + k] - mu * sgw) + bw + bpv;
            float p = 1.0f / (1.0f + expf(-logit));
            float sr = (hp < 1.0f) ? 1.0f : 0.0f;
            float acc = hp + p * sr;
            float nh  = (acc > THRESH)  ? sr : 0.0f;
            sr        = (acc <= THRESH) ? sr : 0.0f;
            hp  += p * sr;
            rem += nh * (1.0f - hp);
            hp  += nh * rem;
            nup += sr + nh;
            uw[k] = p * sr + nh * rem;
        }
        float suf = 1.0f, alpha = 0.0f;
        #pragma unroll
        for (int k = HOP - 1; k >= 0; k--) {
            float gk = uw[k] * suf;
            g_gamma[m * HOP + k] = gk;
            alpha += gk;
            suf *= (1.0f - uw[k]);
        }
        g_alpha[m] = alpha;
        out[(size_t)Mv * Hv + m]      = rem;
        out[(size_t)Mv * Hv + Mv + m] = nup;
    }
}

// =====================================================================
// K3: round Wt -> g_wtr AND compute c_k[o] (exact fp32).
// =====================================================================
__global__ void k_wt(const float* __restrict__ Wt,
                     const float* __restrict__ pos,
                     const float* __restrict__ bt) {
    int o = blockIdx.x, tid = threadIdx.x;
    int warp = tid >> 5, lane = tid & 31;

    float4 v = ((const float4*)(Wt + (size_t)o * Hv))[tid];
    float4 r;
    r.x = __uint_as_float(f2tf(v.x));
    r.y = __uint_as_float(f2tf(v.y));
    r.z = __uint_as_float(f2tf(v.z));
    r.w = __uint_as_float(f2tf(v.w));
    ((float4*)(g_wtr + (size_t)o * Hv))[tid] = r;

    float d[HOP];
    #pragma unroll
    for (int k = 0; k < HOP; k++) {
        float4 p = ((const float4*)(pos + k * Hv))[tid];
        d[k] = v.x * p.x + v.y * p.y + v.z * p.z + v.w * p.w;
    }
    #pragma unroll
    for (int s = 16; s; s >>= 1)
        #pragma unroll
        for (int k = 0; k < HOP; k++)
            d[k] += __shfl_xor_sync(0xffffffffu, d[k], s);

    __shared__ float red[HOP][8];
    if (lane == 0)
        #pragma unroll
        for (int k = 0; k < HOP; k++) red[k][warp] = d[k];
    __syncthreads();
    if (tid < HOP) {
        float s = 0.0f;
        #pragma unroll
        for (int w = 0; w < 8; w++) s += red[tid][w];
        g_c[tid * Hv + o] = s + bt[o];
    }
}

// =====================================================================
// K4: TF32 mma.sync GEMM, 5-stage cp.async ring, ONE barrier per ktile.
//   out[tok][o] = alpha[tok]*(base.Wt^T) + sum_k gamma[tok][k]*c_k[o]
// BM=128 tokens, BN=128 o, BK=16; 8 warps (2M x 4N), warp 64x32.
// k-perm: frag-col t <-> k=4t, t+4 <-> k=4t+1 (s=0); 4t+2/4t+3 (s=1),
// identical on A and B, so B loads as 4x LDS.128 covering both s and
// A s1 loads hide under s0 mma.
// =====================================================================
#define BMT 128
#define BNO 128
#define KTILES 64
#define AS_STRIDE 66                   // uint4 per kp-row (64 + 2 pad)
#define BS_STRIDE 96                   // bytes per n-row (64 + 32 pad)
#define AS_BYTES (8*AS_STRIDE*16)      // 8448
#define STG_BYTES (AS_BYTES + 128*BS_STRIDE)   // 20736
#define NSTG 5
#define RING_BYTES (NSTG*STG_BYTES)    // 103680

__global__ void __launch_bounds__(256, 2) k_gemm(float* __restrict__ out) {
    extern __shared__ char ring[];
    __shared__ float sC[HOP][BNO];

    int tid  = threadIdx.x;
    int lane = tid & 31, wid = tid >> 5;
    int tig  = lane & 3, lrow = lane >> 2;
    int warp_m = wid & 1, warp_n = wid >> 1;
    int n0 = blockIdx.x * BNO;            // o offset
    int m0 = blockIdx.y * BMT;            // token offset
    int j0 = m0 >> 1;                     // token-pair offset

    for (int i = tid; i < HOP * (BNO / 4); i += 256) {
        int k = i >> 5, c4 = i & 31;
        ((float4*)&sC[k][0])[c4] = ((const float4*)&g_c[k * Hv + n0])[c4];
    }

    uint32_t rb = smem_u32(ring);

    // cp.async addressing: one base + const offsets
    const float* asrc = g_basep + ((size_t)(j0 + (tid >> 3)) * 512 + (tid & 7)) * 4;
    uint32_t     adst = rb + ((tid & 7) * AS_STRIDE + (tid >> 3)) * 16;
    const float* bsrc = g_wtr + (size_t)(n0 + (tid >> 2)) * Hv + (tid & 3) * 4;
    uint32_t     bdst = rb + AS_BYTES + (tid >> 2) * BS_STRIDE + (tid & 3) * 16;

    auto issue = [&](int kt, uint32_t soff) {
        if (kt < KTILES) {
            cpasync16(adst + soff,        asrc + kt * 32);
            cpasync16(adst + soff + 512,  asrc + kt * 32 + 65536);   // j+32 (32*512*4)
            cpasync16(bdst + soff,        bsrc + kt * 16);
            cpasync16(bdst + soff + 6144, bsrc + kt * 16 + 65536);   // n+64 (64*Hv)
        }
        CP_COMMIT();
    };

    issue(0, 0);
    issue(1, STG_BYTES);
    issue(2, 2 * STG_BYTES);

    float acc[4][4][4];
    #pragma unroll
    for (int i = 0; i < 4; i++)
        #pragma unroll
        for (int j = 0; j < 4; j++)
            #pragma unroll
            for (int r = 0; r < 4; r++) acc[i][j][r] = 0.0f;

    // per-warp fragment byte offsets within a stage
    uint32_t a_off = (uint32_t)(2 * tig) * (AS_STRIDE * 16) + (warp_m * 32 + lrow) * 16;
    uint32_t b_off = AS_BYTES + (warp_n * 32 + lrow) * BS_STRIDE + tig * 16;

    uint32_t rsoff = 0, wsoff = 3 * STG_BYTES;

    for (int kt = 0; kt < KTILES; kt++) {
        CP_WAIT(2);
        __syncthreads();

        issue(kt + 3, wsoff);
        wsoff += STG_BYTES; if (wsoff == RING_BYTES) wsoff = 0;

        const char* st = ring + rsoff;
        rsoff += STG_BYTES; if (rsoff == RING_BYTES) rsoff = 0;

        // B fragments: uint4 covers k'=4tig..4tig+3 (both s sub-steps)
        uint4 bfr[4];
        #pragma unroll
        for (int j = 0; j < 4; j++)
            bfr[j] = *(const uint4*)(st + b_off + j * (8 * BS_STRIDE));

        // A fragments s=0 (kp-row 2tig: k = 4tig, 4tig+1)
        uint4 af[4];
        #pragma unroll
        for (int i = 0; i < 4; i++)
            af[i] = *(const uint4*)(st + a_off + i * 128);

        #pragma unroll
        for (int i = 0; i < 4; i++)
            #pragma unroll
            for (int j = 0; j < 4; j++)
                mma_tf32(acc[i][j], af[i].x, af[i].y, af[i].z, af[i].w,
                         bfr[j].x, bfr[j].y);

        // A fragments s=1 (kp-row 2tig+1: k = 4tig+2, 4tig+3)
        uint4 ag[4];
        #pragma unroll
        for (int i = 0; i < 4; i++)
            ag[i] = *(const uint4*)(st + a_off + (AS_STRIDE * 16) + i * 128);

        #pragma unroll
        for (int i = 0; i < 4; i++)
            #pragma unroll
            for (int j = 0; j < 4; j++)
                mma_tf32(acc[i][j], ag[i].x, ag[i].y, ag[i].z, ag[i].w,
                         bfr[j].z, bfr[j].w);
    }

    // ---- epilogue: out = alpha*acc + sum_k gamma_k * c_k ----
    #pragma unroll
    for (int i = 0; i < 4; i++) {
        #pragma unroll
        for (int h = 0; h < 2; h++) {
            int tl = (warp_m * 4 + i) * 16 + 2 * lrow + h;
            int gm = m0 + tl;
            float al = g_alpha[gm];
            float4 gA = ((const float4*)(g_gamma + (size_t)gm * HOP))[0];
            float4 gB = ((const float4*)(g_gamma + (size_t)gm * HOP))[1];
            float4 gC = ((const float4*)(g_gamma + (size_t)gm * HOP))[2];
            float gk[HOP] = {gA.x, gA.y, gA.z, gA.w, gB.x, gB.y, gB.z, gB.w,
                             gC.x, gC.y, gC.z, gC.w};
            #pragma unroll
            for (int j = 0; j < 4; j++) {
                int cb = warp_n * 32 + j * 8 + 2 * tig;
                float ex = 0.0f, ey = 0.0f;
                #pragma unroll
                for (int k = 0; k < HOP; k++) {
                    float2 cp = *(const float2*)&sC[k][cb];
                    ex += gk[k] * cp.x;
                    ey += gk[k] * cp.y;
                }
                float2 o;
                o.x = al * acc[i][j][2 * h + 0] + ex;
                o.y = al * acc[i][j][2 * h + 1] + ey;
                *(float2*)&out[(size_t)gm * Hv + n0 + cb] = o;
            }
        }
    }
}

// =====================================================================
extern "C" void kernel_launch(void* const* d_in, const int* in_sizes, int n_in,
                              void* d_out, int out_size) {
    const float* inputs  = (const float*)d_in[0];   // [8,2048,1024]
    const float* time_e  = (const float*)d_in[1];   // [1,2048,1024]
    const float* pos_e   = (const float*)d_in[2];   // [1,12,1024]
    const float* ln_g    = (const float*)d_in[3];   // [1024]
    const float* ln_b    = (const float*)d_in[4];   // [1024]
    const float* w_p     = (const float*)d_in[5];   // [1024]
    const float* b_p     = (const float*)d_in[6];   // [1]
    const float* Wt      = (const float*)d_in[7];   // [1024,1024]
    const float* bt      = (const float*)d_in[8];   // [1024]
    float* out = (float*)d_out;

    cudaFuncSetAttribute(k_gemm, cudaFuncAttributeMaxDynamicSharedMemorySize,
                         RING_BYTES);

    k_scal<<<1, 256>>>(pos_e, ln_g, ln_b, w_p);
    k_token<<<Mv / 8, 256>>>(inputs, time_e, pos_e, ln_g, w_p, b_p, out);
    k_wt<<<Hv, 256>>>(Wt, pos_e, bt);
    k_gemm<<<dim3(Hv / BNO, Mv / BMT), 256, RING_BYTES>>>(out);
}